// round 13
// baseline (speedup 1.0000x reference)
#include <cuda_runtime.h>
#include <stdint.h>
#include <stddef.h>

#define B     64
#define NOISE 128
#define HS    64
#define NH    8
#define MM    4
#define V     32000
#define H     512
#define SI    1024
#define SOS   31999
#define EPS   1e-5f
#define KC    32

__device__ float g_zpre[B*H];
__device__ float g_zh  [B*H];
__device__ float g_s   [B*SI];
__device__ float g_inp [B*H];
__device__ float g_q   [B*MM*H];
__device__ float g_k   [B*5*H];
__device__ float g_v   [B*5*H];
__device__ float g_ao  [B*MM*H];
__device__ float g_h1  [B*MM*H];
__device__ float g_nm  [B*MM*H];
__device__ float g_memA[B*MM*H];
__device__ float g_memB[B*MM*H];
__device__ float g_memT[MM*H*B];
__device__ float g_t   [B*V];
__device__ float g_g   [B*V];
__device__ int   g_prev[B];

static __host__ __device__ __forceinline__
void tf2x32(uint32_t k0, uint32_t k1, uint32_t x0, uint32_t x1,
            uint32_t* o0, uint32_t* o1)
{
    uint32_t ks0 = k0, ks1 = k1, ks2 = k0 ^ k1 ^ 0x1BD11BDAu;
    x0 += ks0; x1 += ks1;
#define TFR(r) { x0 += x1; x1 = (x1 << (r)) | (x1 >> (32 - (r))); x1 ^= x0; }
    TFR(13) TFR(15) TFR(26) TFR(6)   x0 += ks1; x1 += ks2 + 1u;
    TFR(17) TFR(29) TFR(16) TFR(24)  x0 += ks2; x1 += ks0 + 2u;
    TFR(13) TFR(15) TFR(26) TFR(6)   x0 += ks0; x1 += ks1 + 3u;
    TFR(17) TFR(29) TFR(16) TFR(24)  x0 += ks1; x1 += ks2 + 4u;
    TFR(13) TFR(15) TFR(26) TFR(6)   x0 += ks2; x1 += ks0 + 5u;
#undef TFR
    *o0 = x0; *o1 = x1;
}

__device__ __forceinline__ float gumbel_from_bits(uint32_t bits)
{
    float f = __uint_as_float((bits >> 9) | 0x3f800000u) - 1.0f;
    const float tiny = 1.17549435e-38f;
    float u = fmaxf(tiny, f + tiny);
    return -logf(-logf(u));
}

__device__ __forceinline__ float lrelu(float x) { return x > 0.0f ? x : 0.2f * x; }

__global__ void k_init()
{
    int t = blockIdx.x * blockDim.x + threadIdx.x;
    if (t < B) g_prev[t] = SOS;
    int stride = gridDim.x * blockDim.x;
    for (int i = t; i < B * MM * H; i += stride) {
        int h = i % H;
        int m = (i / H) % MM;
        g_memA[i] = (h == m) ? 1.0f : 0.0f;
    }
}

__global__ void k_zpre(const float* __restrict__ z, const float* __restrict__ w,
                       const float* __restrict__ bias)
{
    __shared__ float sz[NOISE];
    int b = blockIdx.x, t = threadIdx.x;
    if (t < NOISE) sz[t] = z[b * NOISE + t];
    __syncthreads();
    int h4 = t * 4;
    float4 acc = *(const float4*)(bias + h4);
    for (int k = 0; k < NOISE; k++) {
        float s = sz[k];
        float4 w4 = *(const float4*)(w + k * H + h4);
        acc.x = fmaf(s, w4.x, acc.x); acc.y = fmaf(s, w4.y, acc.y);
        acc.z = fmaf(s, w4.z, acc.z); acc.w = fmaf(s, w4.w, acc.w);
    }
    float* dst = g_zpre + b * H + h4;
    dst[0] = lrelu(acc.x); dst[1] = lrelu(acc.y);
    dst[2] = lrelu(acc.z); dst[3] = lrelu(acc.w);
}

__global__ void k_bn1(const float* __restrict__ g, const float* __restrict__ bb)
{
    int c = blockIdx.x * blockDim.x + threadIdx.x;
    if (c >= H) return;
    float mu = 0.0f;
    for (int b = 0; b < B; b++) mu += g_zpre[b * H + c];
    mu *= (1.0f / B);
    float var = 0.0f;
    for (int b = 0; b < B; b++) { float d = g_zpre[b * H + c] - mu; var += d * d; }
    var *= (1.0f / B);
    float sc = g[c] * rsqrtf(var + EPS);
    float bc = bb[c];
    for (int b = 0; b < B; b++)
        g_zh[b * H + c] = sc * (g_zpre[b * H + c] - mu) + bc;
}

__device__ __forceinline__ float sval(const float* __restrict__ emb, int c, int b)
{
    if (c < H) return lrelu(emb[(size_t)g_prev[b] * H + c]);
    return g_zh[b * H + c - H];
}

__global__ void k_embed_bn(const float* __restrict__ emb,
                           const float* __restrict__ g2, const float* __restrict__ b2)
{
    int c = blockIdx.x * blockDim.x + threadIdx.x;
    if (c >= SI) return;
    float mu = 0.0f;
    for (int b = 0; b < B; b++) mu += sval(emb, c, b);
    mu *= (1.0f / B);
    float var = 0.0f;
    for (int b = 0; b < B; b++) { float d = sval(emb, c, b) - mu; var += d * d; }
    var *= (1.0f / B);
    float sc = g2[c] * rsqrtf(var + EPS);
    float bc = b2[c];
    for (int b = 0; b < B; b++)
        g_s[b * SI + c] = sc * (sval(emb, c, b) - mu) + bc;
}

__global__ void k_inp(const float* __restrict__ w, const float* __restrict__ bias)
{
    __shared__ float ss[SI];
    int b = blockIdx.x, t = threadIdx.x;
    for (int i = t; i < SI; i += 128) ss[i] = g_s[b * SI + i];
    __syncthreads();
    int h4 = t * 4;
    float4 acc = *(const float4*)(bias + h4);
    for (int k = 0; k < SI; k++) {
        float s = ss[k];
        float4 w4 = *(const float4*)(w + k * H + h4);
        acc.x = fmaf(s, w4.x, acc.x); acc.y = fmaf(s, w4.y, acc.y);
        acc.z = fmaf(s, w4.z, acc.z); acc.w = fmaf(s, w4.w, acc.w);
    }
    *(float4*)(g_inp + b * H + h4) = acc;
}

__global__ void k_qkv(int ping, const float* __restrict__ wq,
                      const float* __restrict__ wk, const float* __restrict__ wv)
{
    const float* memIn = ping ? g_memB : g_memA;
    int b = blockIdx.x, j = blockIdx.y, t = threadIdx.x;
    const float* src; const float* W; float* dst;
    if (j < 4) {
        src = memIn + (b * MM + j) * H; W = wq; dst = g_q + (b * MM + j) * H;
    } else if (j < 9) {
        int n = j - 4;
        src = (n < 4) ? (memIn + (b * MM + n) * H) : (g_inp + b * H);
        W = wk; dst = g_k + (b * 5 + n) * H;
    } else {
        int n = j - 9;
        src = (n < 4) ? (memIn + (b * MM + n) * H) : (g_inp + b * H);
        W = wv; dst = g_v + (b * 5 + n) * H;
    }
    __shared__ float ss[H];
    for (int i = t; i < H; i += 128) ss[i] = src[i];
    __syncthreads();
    int h4 = t * 4;
    float4 acc = make_float4(0.f, 0.f, 0.f, 0.f);
    for (int k = 0; k < H; k++) {
        float s = ss[k];
        float4 w4 = *(const float4*)(W + k * H + h4);
        acc.x = fmaf(s, w4.x, acc.x); acc.y = fmaf(s, w4.y, acc.y);
        acc.z = fmaf(s, w4.z, acc.z); acc.w = fmaf(s, w4.w, acc.w);
    }
    *(float4*)(dst + h4) = acc;
}

__global__ void k_attn()
{
    int b = blockIdx.x, hd = blockIdx.y, t = threadIdx.x;
    __shared__ float qs[4][HS], ks[5][HS], vs[5][HS], att[4][5];
    int m = t >> 6, d = t & 63;
    qs[m][d] = g_q[(b * MM + m) * H + hd * HS + d];
    ks[m][d] = g_k[(b * 5 + m) * H + hd * HS + d];
    vs[m][d] = g_v[(b * 5 + m) * H + hd * HS + d];
    if (t < 64) {
        ks[4][t] = g_k[(b * 5 + 4) * H + hd * HS + t];
        vs[4][t] = g_v[(b * 5 + 4) * H + hd * HS + t];
    }
    __syncthreads();
    if (t < 20) {
        int mm = t / 5, nn = t % 5;
        float s = 0.f;
        for (int i = 0; i < HS; i++) s += qs[mm][i] * ks[nn][i];
        att[mm][nn] = s * 0.125f;
    }
    __syncthreads();
    if (t < 4) {
        float mx = att[t][0];
        for (int n = 1; n < 5; n++) mx = fmaxf(mx, att[t][n]);
        float e[5], sum = 0.f;
        for (int n = 0; n < 5; n++) { e[n] = expf(att[t][n] - mx); sum += e[n]; }
        for (int n = 0; n < 5; n++) att[t][n] = e[n] / sum;
    }
    __syncthreads();
    float acc = 0.f;
    for (int n = 0; n < 5; n++) acc += att[m][n] * vs[n][d];
    g_ao[(b * MM + m) * H + hd * HS + d] = acc;
}

__global__ void k_mlp1(int ping, const float* __restrict__ w, const float* __restrict__ bias)
{
    const float* memIn = ping ? g_memB : g_memA;
    int b = blockIdx.x, m = blockIdx.y, t = threadIdx.x;
    __shared__ float ss[H];
    int base = (b * MM + m) * H;
    for (int i = t; i < H; i += 128) {
        float v = memIn[base + i] + g_ao[base + i];
        ss[i] = v; g_nm[base + i] = v;
    }
    __syncthreads();
    int h4 = t * 4;
    float4 acc = *(const float4*)(bias + h4);
    for (int k = 0; k < H; k++) {
        float s = ss[k];
        float4 w4 = *(const float4*)(w + k * H + h4);
        acc.x = fmaf(s, w4.x, acc.x); acc.y = fmaf(s, w4.y, acc.y);
        acc.z = fmaf(s, w4.z, acc.z); acc.w = fmaf(s, w4.w, acc.w);
    }
    float* dst = g_h1 + base + h4;
    dst[0] = lrelu(acc.x); dst[1] = lrelu(acc.y);
    dst[2] = lrelu(acc.z); dst[3] = lrelu(acc.w);
}

__global__ void k_mlp2g(int ping, const float* __restrict__ w, const float* __restrict__ bias,
                        const float* __restrict__ w_gx, const float* __restrict__ b_gx,
                        const float* __restrict__ w_gm)
{
    const float* memIn = ping ? g_memB : g_memA;
    float*      memOut = ping ? g_memA : g_memB;
    int b = blockIdx.x, m = blockIdx.y, t = threadIdx.x;
    __shared__ float h1s[H];
    __shared__ float red[128][4];
    __shared__ float ig_s, fg_s;
    int base = (b * MM + m) * H;
    for (int i = t; i < H; i += 128) h1s[i] = g_h1[base + i];
    float p0 = 0.f, p1 = 0.f, p2 = 0.f, p3 = 0.f;
    for (int k = t; k < H; k += 128) {
        float tm = tanhf(memIn[base + k]);
        p0 = fmaf(tm, w_gm[k * 2 + 0], p0);
        p1 = fmaf(tm, w_gm[k * 2 + 1], p1);
        float iv = g_inp[b * H + k];
        p2 = fmaf(iv, w_gx[k * 2 + 0], p2);
        p3 = fmaf(iv, w_gx[k * 2 + 1], p3);
    }
    red[t][0] = p0; red[t][1] = p1; red[t][2] = p2; red[t][3] = p3;
    __syncthreads();
    if (t == 0) {
        float s0 = 0.f, s1 = 0.f, s2 = 0.f, s3 = 0.f;
        for (int i = 0; i < 128; i++) {
            s0 += red[i][0]; s1 += red[i][1]; s2 += red[i][2]; s3 += red[i][3];
        }
        float g0 = s2 + b_gx[0] + s0;
        float g1 = s3 + b_gx[1] + s1 + 1.0f;
        ig_s = 1.f / (1.f + expf(-g0));
        fg_s = 1.f / (1.f + expf(-g1));
    }
    __syncthreads();
    int h4 = t * 4;
    float4 acc = *(const float4*)(bias + h4);
    for (int k = 0; k < H; k++) {
        float s = h1s[k];
        float4 w4 = *(const float4*)(w + k * H + h4);
        acc.x = fmaf(s, w4.x, acc.x); acc.y = fmaf(s, w4.y, acc.y);
        acc.z = fmaf(s, w4.z, acc.z); acc.w = fmaf(s, w4.w, acc.w);
    }
    float ig = ig_s, fg = fg_s;
    float a4[4] = {acc.x, acc.y, acc.z, acc.w};
#pragma unroll
    for (int u = 0; u < 4; u++) {
        int h = h4 + u;
        float nm2 = g_nm[base + h] + a4[u];
        float nv = fg * memIn[base + h] + ig * tanhf(nm2);
        memOut[base + h] = nv;
        g_memT[(m * H + h) * B + b] = nv;
    }
}

// JAX partitionable threefry, 32-bit draws:
// counts = (hi32(j), lo32(j)) = (0, j);  bits = bits1 ^ bits2  (XOR of both lanes)
__global__ void k_gumbel(unsigned k0, unsigned k1)
{
    unsigned j = blockIdx.x * blockDim.x + threadIdx.x;
    if (j >= (unsigned)(B * V)) return;
    unsigned o0, o1;
    tf2x32(k0, k1, 0u, j, &o0, &o1);
    g_g[j] = gumbel_from_bits(o0 ^ o1);
}

__global__ void __launch_bounds__(256) k_logits(const float* __restrict__ W,
                                                const float* __restrict__ bias)
{
    __shared__ float As[KC][B];
    __shared__ float Ws[KC][128];
    int n0 = blockIdx.x * 128;
    int t = threadIdx.x;
    int r = t >> 5;
    int c = t & 31;
    float acc[8][4];
#pragma unroll
    for (int i = 0; i < 8; i++)
#pragma unroll
        for (int j = 0; j < 4; j++) acc[i][j] = 0.f;

    for (int kt = 0; kt < MM * H; kt += KC) {
#pragma unroll
        for (int l = 0; l < 8; l++) {
            int e = t + l * 256;
            int kk = e >> 6, row = e & 63;
            As[kk][row] = g_memT[(kt + kk) * B + row];
        }
#pragma unroll
        for (int l = 0; l < 4; l++) {
            int e = t + l * 256;
            int kk = e >> 5;
            int c4 = (e & 31) * 4;
            *(float4*)&Ws[kk][c4] =
                *(const float4*)&W[(size_t)(kt + kk) * V + n0 + c4];
        }
        __syncthreads();
#pragma unroll
        for (int kk = 0; kk < KC; kk++) {
            float4 a0 = *(float4*)&As[kk][4 * r];
            float4 a1 = *(float4*)&As[kk][4 * r + 32];
            float4 w4 = *(float4*)&Ws[kk][c * 4];
            float av[8] = {a0.x, a0.y, a0.z, a0.w, a1.x, a1.y, a1.z, a1.w};
            float wv[4] = {w4.x, w4.y, w4.z, w4.w};
#pragma unroll
            for (int i = 0; i < 8; i++)
#pragma unroll
                for (int j = 0; j < 4; j++)
                    acc[i][j] = fmaf(av[i], wv[j], acc[i][j]);
        }
        __syncthreads();
    }
    float4 bb = *(const float4*)&bias[n0 + c * 4];
    float bv[4] = {bb.x, bb.y, bb.z, bb.w};
#pragma unroll
    for (int i = 0; i < 8; i++) {
        int row = 4 * r + (i < 4 ? i : 32 + i - 4);
        float4 o;
        o.x = acc[i][0] + bv[0]; o.y = acc[i][1] + bv[1];
        o.z = acc[i][2] + bv[2]; o.w = acc[i][3] + bv[3];
        *(float4*)&g_t[(size_t)row * V + n0 + c * 4] = o;
    }
}

__global__ void k_softmax(float* __restrict__ out, int step, int steps,
                          const int* __restrict__ tptr)
{
    int b = blockIdx.x, t = threadIdx.x;
    int tb = *tptr;
    float temp = (tb >= 1 && tb < 100000) ? (float)tb : __int_as_float(tb);
    float inv = 1.0f / temp;
    const float* lg = g_t + (size_t)b * V;
    const float* gg = g_g + (size_t)b * V;
    __shared__ float smx[256]; __shared__ int sai[256]; __shared__ float ssum[256];
    float mx = -1e30f; int ai = 0;
    for (int v = t; v < V; v += 256) {
        float x = (lg[v] + gg[v]) * inv;
        if (x > mx) { mx = x; ai = v; }
    }
    smx[t] = mx; sai[t] = ai;
    __syncthreads();
    for (int o = 128; o > 0; o >>= 1) {
        if (t < o) {
            if (smx[t + o] > smx[t] ||
                (smx[t + o] == smx[t] && sai[t + o] < sai[t])) {
                smx[t] = smx[t + o]; sai[t] = sai[t + o];
            }
        }
        __syncthreads();
    }
    float rowmax = smx[0];
    if (t == 0) g_prev[b] = sai[0];
    float s = 0.f;
    for (int v = t; v < V; v += 256) s += expf((lg[v] + gg[v]) * inv - rowmax);
    ssum[t] = s;
    __syncthreads();
    for (int o = 128; o > 0; o >>= 1) {
        if (t < o) ssum[t] += ssum[t + o];
        __syncthreads();
    }
    float rinv = 1.0f / ssum[0];
    float* op = out + ((size_t)b * steps + step) * V;
    for (int v = t; v < V; v += 256)
        op[v] = expf((lg[v] + gg[v]) * inv - rowmax) * rinv;
}

extern "C" void kernel_launch(void* const* d_in, const int* in_sizes, int n_in,
                              void* d_out, int out_size)
{
    const float* z     = (const float*)d_in[0];
    const float* w_z2m = (const float*)d_in[1];
    const float* b_z2m = (const float*)d_in[2];
    const float* bn1_g = (const float*)d_in[3];
    const float* bn1_b = (const float*)d_in[4];
    const float* emb   = (const float*)d_in[5];
    const float* bn2_g = (const float*)d_in[6];
    const float* bn2_b = (const float*)d_in[7];
    const float* w_in  = (const float*)d_in[8];
    const float* b_in  = (const float*)d_in[9];
    const float* w_q   = (const float*)d_in[10];
    const float* w_k   = (const float*)d_in[11];
    const float* w_v   = (const float*)d_in[12];
    const float* w_m1  = (const float*)d_in[13];
    const float* b_m1  = (const float*)d_in[14];
    const float* w_m2  = (const float*)d_in[15];
    const float* b_m2  = (const float*)d_in[16];
    const float* w_gx  = (const float*)d_in[17];
    const float* b_gx  = (const float*)d_in[18];
    const float* w_gm  = (const float*)d_in[19];
    const float* w_m2o = (const float*)d_in[20];
    const float* b_m2o = (const float*)d_in[21];
    const int*   tptr  = (const int*)d_in[23];
    float* out = (float*)d_out;
    int steps = out_size / (B * V);

    k_init<<<512, 256>>>();
    k_zpre<<<B, 128>>>(z, w_z2m, b_z2m);
    k_bn1<<<4, 128>>>(bn1_g, bn1_b);

    for (int s = 0; s < steps; s++) {
        unsigned fk0, fk1;
        tf2x32(0u, 42u, 0u, (unsigned)s, &fk0, &fk1);
        int ping = s & 1;

        k_embed_bn<<<8, 128>>>(emb, bn2_g, bn2_b);
        k_inp<<<B, 128>>>(w_in, b_in);
        k_qkv<<<dim3(B, 14), 128>>>(ping, w_q, w_k, w_v);
        k_attn<<<dim3(B, NH), 256>>>();
        k_mlp1<<<dim3(B, MM), 128>>>(ping, w_m1, b_m1);
        k_mlp2g<<<dim3(B, MM), 128>>>(ping, w_m2, b_m2, w_gx, b_gx, w_gm);
        k_gumbel<<<(B * V + 255) / 256, 256>>>(fk0, fk1);
        k_logits<<<V / 128, 256>>>(w_m2o, b_m2o);
        k_softmax<<<B, 256>>>(out, s, steps, tptr);
    }
}

// round 14
// speedup vs baseline: 1.0678x; 1.0678x over previous
#include <cuda_runtime.h>
#include <cuda_bf16.h>
#include <stdint.h>
#include <stddef.h>

#define B 64
#define NOISE 128
#define HS 64
#define NH 8
#define MM 4
#define V 32000
#define H 512
#define SI 1024
#define SOS 31999
#define EPS 1e-5f
#define KV 2048
#define NT 128

__device__ float g_zpre[B*H];
__device__ float g_zh[B*H];
__device__ float g_s[B*SI];
__device__ float g_inp[B*H];
__device__ float g_q[B*MM*H];
__device__ float g_k[B*5*H];
__device__ float g_v[B*5*H];
__device__ float g_ao[B*MM*H];
__device__ float g_h1[B*MM*H];
__device__ float g_nm[B*MM*H];
__device__ float g_memA[B*MM*H];
__device__ float g_memB[B*MM*H];
__device__ float g_t[B*V];
__device__ float g_g[B*V];
__device__ int g_prev[B];
__device__ __nv_bfloat16 g_As[3*B*KV];
__device__ __nv_bfloat16 g_W1[(size_t)KV*V];
__device__ __nv_bfloat16 g_W2[(size_t)KV*V];
__device__ __nv_bfloat16 g_W3[(size_t)KV*V];

static __host__ __device__ __forceinline__
void tf2x32(uint32_t k0, uint32_t k1, uint32_t x0, uint32_t x1,
            uint32_t* o0, uint32_t* o1)
{
    uint32_t ks0 = k0, ks1 = k1, ks2 = k0 ^ k1 ^ 0x1BD11BDAu;
    x0 += ks0; x1 += ks1;
#define TFR(r) { x0 += x1; x1 = (x1 << (r)) | (x1 >> (32 - (r))); x1 ^= x0; }
    TFR(13) TFR(15) TFR(26) TFR(6)   x0 += ks1; x1 += ks2 + 1u;
    TFR(17) TFR(29) TFR(16) TFR(24)  x0 += ks2; x1 += ks0 + 2u;
    TFR(13) TFR(15) TFR(26) TFR(6)   x0 += ks0; x1 += ks1 + 3u;
    TFR(17) TFR(29) TFR(16) TFR(24)  x0 += ks1; x1 += ks2 + 4u;
    TFR(13) TFR(15) TFR(26) TFR(6)   x0 += ks2; x1 += ks0 + 5u;
#undef TFR
    *o0 = x0; *o1 = x1;
}

__device__ __forceinline__ float gumbel_from_bits(uint32_t bits)
{
    float f = __uint_as_float((bits >> 9) | 0x3f800000u) - 1.0f;
    const float tiny = 1.17549435e-38f;
    float u = fmaxf(tiny, f + tiny);
    return -logf(-logf(u));
}

__device__ __forceinline__ float lrelu(float x) { return x > 0.0f ? x : 0.2f * x; }

__global__ void k_init()
{
    int t = blockIdx.x * blockDim.x + threadIdx.x;
    if (t < B) g_prev[t] = SOS;
    int stride = gridDim.x * blockDim.x;
    for (int i = t; i < B * MM * H; i += stride) {
        int h = i % H;
        int m = (i / H) % MM;
        g_memA[i] = (h == m) ? 1.0f : 0.0f;
    }
}

__global__ void k_wsplit(const float* __restrict__ W)
{
    size_t i = ((size_t)blockIdx.x * 256 + threadIdx.x) * 4;
    if (i >= (size_t)KV * V) return;
    float4 w4 = *(const float4*)(W + i);
    float x[4] = {w4.x, w4.y, w4.z, w4.w};
    __nv_bfloat16 h1[4], h2[4], h3[4];
#pragma unroll
    for (int u = 0; u < 4; u++) {
        __nv_bfloat16 a = __float2bfloat16(x[u]);
        float r = x[u] - __bfloat162float(a);
        __nv_bfloat16 b = __float2bfloat16(r);
        float r2 = r - __bfloat162float(b);
        h1[u] = a; h2[u] = b; h3[u] = __float2bfloat16(r2);
    }
    ((__nv_bfloat162*)(g_W1 + i))[0] = __nv_bfloat162(h1[0], h1[1]);
    ((__nv_bfloat162*)(g_W1 + i))[1] = __nv_bfloat162(h1[2], h1[3]);
    ((__nv_bfloat162*)(g_W2 + i))[0] = __nv_bfloat162(h2[0], h2[1]);
    ((__nv_bfloat162*)(g_W2 + i))[1] = __nv_bfloat162(h2[2], h2[3]);
    ((__nv_bfloat162*)(g_W3 + i))[0] = __nv_bfloat162(h3[0], h3[1]);
    ((__nv_bfloat162*)(g_W3 + i))[1] = __nv_bfloat162(h3[2], h3[3]);
}

__global__ void k_zpre(const float* __restrict__ z, const float* __restrict__ w,
                       const float* __restrict__ bias)
{
    __shared__ float sz[NOISE];
    int b = blockIdx.x, t = threadIdx.x;
    if (t < NOISE) sz[t] = z[b * NOISE + t];
    __syncthreads();
    int h4 = t * 4;
    float4 acc = *(const float4*)(bias + h4);
    for (int k = 0; k < NOISE; k++) {
        float s = sz[k];
        float4 w4 = *(const float4*)(w + k * H + h4);
        acc.x = fmaf(s, w4.x, acc.x); acc.y = fmaf(s, w4.y, acc.y);
        acc.z = fmaf(s, w4.z, acc.z); acc.w = fmaf(s, w4.w, acc.w);
    }
    float* dst = g_zpre + b * H + h4;
    dst[0] = lrelu(acc.x); dst[1] = lrelu(acc.y);
    dst[2] = lrelu(acc.z); dst[3] = lrelu(acc.w);
}

__global__ void k_bn1(const float* __restrict__ g, const float* __restrict__ bb)
{
    int c = blockIdx.x * blockDim.x + threadIdx.x;
    if (c >= H) return;
    float mu = 0.0f;
    for (int b = 0; b < B; b++) mu += g_zpre[b * H + c];
    mu *= (1.0f / B);
    float var = 0.0f;
    for (int b = 0; b < B; b++) { float d = g_zpre[b * H + c] - mu; var += d * d; }
    var *= (1.0f / B);
    float sc = g[c] * rsqrtf(var + EPS);
    float bc = bb[c];
    for (int b = 0; b < B; b++)
        g_zh[b * H + c] = sc * (g_zpre[b * H + c] - mu) + bc;
}

__device__ __forceinline__ float sval(const float* __restrict__ emb, int c, int b)
{
    if (c < H) return lrelu(emb[(size_t)g_prev[b] * H + c]);
    return g_zh[b * H + c - H];
}

__global__ void k_embed_bn(const float* __restrict__ emb,
                           const float* __restrict__ g2, const float* __restrict__ b2)
{
    int c = blockIdx.x * blockDim.x + threadIdx.x;
    if (c >= SI) return;
    float mu = 0.0f;
    for (int b = 0; b < B; b++) mu += sval(emb, c, b);
    mu *= (1.0f / B);
    float var = 0.0f;
    for (int b = 0; b < B; b++) { float d = sval(emb, c, b) - mu; var += d * d; }
    var *= (1.0f / B);
    float sc = g2[c] * rsqrtf(var + EPS);
    float bc = b2[c];
    for (int b = 0; b < B; b++)
        g_s[b * SI + c] = sc * (sval(emb, c, b) - mu) + bc;
}

__global__ void k_inp(const float* __restrict__ w, const float* __restrict__ bias)
{
    __shared__ float ss[SI];
    int b = blockIdx.x, t = threadIdx.x;
    for (int i = t; i < SI; i += 128) ss[i] = g_s[b * SI + i];
    __syncthreads();
    int h4 = t * 4;
    float4 acc = *(const float4*)(bias + h4);
    for (int k = 0; k < SI; k++) {
        float s = ss[k];
        float4 w4 = *(const float4*)(w + k * H + h4);
        acc.x = fmaf(s, w4.x, acc.x); acc.y = fmaf(s, w4.y, acc.y);
        acc.z = fmaf(s, w4.z, acc.z); acc.w = fmaf(s, w4.w, acc.w);
    }
    *(float4*)(g_inp + b * H + h4) = acc;
}

__global__ void k_qkv(int ping, const float* __restrict__ wq,
                      const float* __restrict__ wk, const float* __restrict__ wv)
{
    const float* memIn = ping ? g_memB : g_memA;
    int b = blockIdx.x, j = blockIdx.y, t = threadIdx.x;
    const float* src; const float* W; float* dst;
    if (j < 4) {
        src = memIn + (b * MM + j) * H; W = wq; dst = g_q + (b * MM + j) * H;
    } else if (j < 9) {
        int n = j - 4;
        src = (n < 4) ? (memIn + (b * MM + n) * H) : (g_inp + b * H);
        W = wk; dst = g_k + (b * 5 + n) * H;
    } else {
        int n = j - 9;
        src = (n < 4) ? (memIn + (b * MM + n) * H) : (g_inp + b * H);
        W = wv; dst = g_v + (b * 5 + n) * H;
    }
    __shared__ float ss[H];
    for (int i = t; i < H; i += 128) ss[i] = src[i];
    __syncthreads();
    int h4 = t * 4;
    float4 acc = make_float4(0.f, 0.f, 0.f, 0.f);
    for (int k = 0; k < H; k++) {
        float s = ss[k];
        float4 w4 = *(const float4*)(W + k * H + h4);
        acc.x = fmaf(s, w4.x, acc.x); acc.y = fmaf(s, w4.y, acc.y);
        acc.z = fmaf(s, w4.z, acc.z); acc.w = fmaf(s, w4.w, acc.w);
    }
    *(float4*)(dst + h4) = acc;
}

__global__ void k_attn()
{
    int b = blockIdx.x, hd = blockIdx.y, t = threadIdx.x;
    __shared__ float qs[4][HS], ks[5][HS], vs[5][HS], att[4][5];
    int m = t >> 6, d = t & 63;
    qs[m][d] = g_q[(b * MM + m) * H + hd * HS + d];
    ks[m][d] = g_k[(b * 5 + m) * H + hd * HS + d];
    vs[m][d] = g_v[(b * 5 + m) * H + hd * HS + d];
    if (t < 64) {
        ks[4][t] = g_k[(b * 5 + 4) * H + hd * HS + t];
        vs[4][t] = g_v[(b * 5 + 4) * H + hd * HS + t];
    }
    __syncthreads();
    if (t < 20) {
        int mm = t / 5, nn = t % 5;
        float s = 0.f;
        for (int i = 0; i < HS; i++) s += qs[mm][i] * ks[nn][i];
        att[mm][nn] = s * 0.125f;
    }
    __syncthreads();
    if (t < 4) {
        float mx = att[t][0];
        for (int n = 1; n < 5; n++) mx = fmaxf(mx, att[t][n]);
        float e[5], sum = 0.f;
        for (int n = 0; n < 5; n++) { e[n] = expf(att[t][n] - mx); sum += e[n]; }
        for (int n = 0; n < 5; n++) att[t][n] = e[n] / sum;
    }
    __syncthreads();
    float acc = 0.f;
    for (int n = 0; n < 5; n++) acc += att[m][n] * vs[n][d];
    g_ao[(b * MM + m) * H + hd * HS + d] = acc;
}

__global__ void k_mlp1(int ping, const float* __restrict__ w, const float* __restrict__ bias)
{
    const float* memIn = ping ? g_memB : g_memA;
    int b = blockIdx.x, m = blockIdx.y, t = threadIdx.x;
    __shared__ float ss[H];
    int base = (b * MM + m) * H;
    for (int i = t; i < H; i += 128) {
        float v = memIn[base + i] + g_ao[base + i];
        ss[i] = v; g_nm[base + i] = v;
    }
    __syncthreads();
    int h4 = t * 4;
    float4 acc = *(const float4*)(bias + h4);
    for (int k = 0; k < H; k++) {
        float s = ss[k];
        float4 w4 = *(const float4*)(w + k * H + h4);
        acc.x = fmaf(s, w4.x, acc.x); acc.y = fmaf(s, w4.y, acc.y);
        acc.z = fmaf(s, w4.z, acc.z); acc.w = fmaf(s, w4.w, acc.w);
    }
    float* dst = g_h1 + base + h4;
    dst[0] = lrelu(acc.x); dst[1] = lrelu(acc.y);
    dst[2] = lrelu(acc.z); dst[3] = lrelu(acc.w);
}

__global__ void k_mlp2g(int ping, const float* __restrict__ w, const float* __restrict__ bias,
                        const float* __restrict__ w_gx, const float* __restrict__ b_gx,
                        const float* __restrict__ w_gm)
{
    const float* memIn = ping ? g_memB : g_memA;
    float*      memOut = ping ? g_memA : g_memB;
    int b = blockIdx.x, m = blockIdx.y, t = threadIdx.x;
    __shared__ float h1s[H];
    __shared__ float red[128][4];
    __shared__ float ig_s, fg_s;
    int base = (b * MM + m) * H;
    for (int i = t; i < H; i += 128) h1s[i] = g_h1[base + i];
    float p0 = 0.f, p1 = 0.f, p2 = 0.f, p3 = 0.f;
    for (int k = t; k < H; k += 128) {
        float tm = tanhf(memIn[base + k]);
        p0 = fmaf(tm, w_gm[k * 2 + 0], p0);
        p1 = fmaf(tm, w_gm[k * 2 + 1], p1);
        float iv = g_inp[b * H + k];
        p2 = fmaf(iv, w_gx[k * 2 + 0], p2);
        p3 = fmaf(iv, w_gx[k * 2 + 1], p3);
    }
    red[t][0] = p0; red[t][1] = p1; red[t][2] = p2; red[t][3] = p3;
    __syncthreads();
    if (t == 0) {
        float s0 = 0.f, s1 = 0.f, s2 = 0.f, s3 = 0.f;
        for (int i = 0; i < 128; i++) {
            s0 += red[i][0]; s1 += red[i][1]; s2 += red[i][2]; s3 += red[i][3];
        }
        float g0 = s2 + b_gx[0] + s0;
        float g1 = s3 + b_gx[1] + s1 + 1.0f;
        ig_s = 1.f / (1.f + expf(-g0));
        fg_s = 1.f / (1.f + expf(-g1));
    }
    __syncthreads();
    int h4 = t * 4;
    float4 acc = *(const float4*)(bias + h4);
    for (int k = 0; k < H; k++) {
        float s = h1s[k];
        float4 w4 = *(const float4*)(w + k * H + h4);
        acc.x = fmaf(s, w4.x, acc.x); acc.y = fmaf(s, w4.y, acc.y);
        acc.z = fmaf(s, w4.z, acc.z); acc.w = fmaf(s, w4.w, acc.w);
    }
    float ig = ig_s, fg = fg_s;
    float a4[4] = {acc.x, acc.y, acc.z, acc.w};
#pragma unroll
    for (int u = 0; u < 4; u++) {
        int h = h4 + u;
        float nm2 = g_nm[base + h] + a4[u];
        float nv = fg * memIn[base + h] + ig * tanhf(nm2);
        memOut[base + h] = nv;
        __nv_bfloat16 s1b = __float2bfloat16(nv);
        float r = nv - __bfloat162float(s1b);
        __nv_bfloat16 s2b = __float2bfloat16(r);
        float r2 = r - __bfloat162float(s2b);
        int kk = m * H + h;
        g_As[(size_t)b * KV + kk]             = s1b;
        g_As[(size_t)(B + b) * KV + kk]       = s2b;
        g_As[(size_t)(2 * B + b) * KV + kk]   = __float2bfloat16(r2);
    }
}

__global__ void k_gumbel(unsigned k0, unsigned k1)
{
    unsigned j = blockIdx.x * blockDim.x + threadIdx.x;
    if (j >= (unsigned)(B * V)) return;
    unsigned o0, o1;
    tf2x32(k0, k1, 0u, j, &o0, &o1);
    g_g[j] = gumbel_from_bits(o0 ^ o1);
}

// ---- tensor-core logits: [64,2048]x[2048,32000], bf16 3-split, 6 products ----
__device__ __forceinline__ void mma16816(float* d, const unsigned* a, const unsigned* b)
{
    asm volatile("mma.sync.aligned.m16n8k16.row.col.f32.bf16.bf16.f32 "
        "{%0,%1,%2,%3},{%4,%5,%6,%7},{%8,%9},{%0,%1,%2,%3};"
        : "+f"(d[0]), "+f"(d[1]), "+f"(d[2]), "+f"(d[3])
        : "r"(a[0]), "r"(a[1]), "r"(a[2]), "r"(a[3]), "r"(b[0]), "r"(b[1]));
}
__device__ __forceinline__ void ldmA4(unsigned* r, unsigned a)
{
    asm volatile("ldmatrix.sync.aligned.m8n8.x4.shared.b16 {%0,%1,%2,%3},[%4];"
        : "=r"(r[0]), "=r"(r[1]), "=r"(r[2]), "=r"(r[3]) : "r"(a));
}
__device__ __forceinline__ void ldmB2T(unsigned* r, unsigned a)
{
    asm volatile("ldmatrix.sync.aligned.m8n8.x2.trans.shared.b16 {%0,%1},[%2];"
        : "=r"(r[0]), "=r"(r[1]) : "r"(a));
}

#define SA_STR 72
#define SW_STR 136
#define SA_SPL (64 * SA_STR)
#define SW_SPL (64 * SW_STR)
#define SMEMB ((3 * SA_SPL + 3 * SW_SPL) * 2)

extern __shared__ __nv_bfloat16 s_dyn[];

__global__ void __launch_bounds__(256) k_logits_mma(const float* __restrict__ bias)
{
    __nv_bfloat16* sA = s_dyn;
    __nv_bfloat16* sW = s_dyn + 3 * SA_SPL;
    int t = threadIdx.x, w = t >> 5, lane = t & 31;
    int n0 = blockIdx.x * NT;
    float acc[4][2][4];
#pragma unroll
    for (int i = 0; i < 4; i++)
#pragma unroll
        for (int j = 0; j < 2; j++)
#pragma unroll
            for (int q = 0; q < 4; q++) acc[i][j][q] = 0.f;

    for (int kt = 0; kt < KV; kt += 64) {
        for (int e = t; e < 3 * 64 * 8; e += 256) {
            int spl = e >> 9, m = (e >> 3) & 63, f = e & 7;
            *(float4*)&sA[spl * SA_SPL + m * SA_STR + f * 8] =
                *(const float4*)&g_As[(size_t)(spl * B + m) * KV + kt + f * 8];
        }
        for (int e = t; e < 64 * 16; e += 256) {
            int k = e >> 4, f = e & 15;
            size_t gi = (size_t)(kt + k) * V + n0 + f * 8;
            *(float4*)&sW[0 * SW_SPL + k * SW_STR + f * 8] = *(const float4*)&g_W1[gi];
            *(float4*)&sW[1 * SW_SPL + k * SW_STR + f * 8] = *(const float4*)&g_W2[gi];
            *(float4*)&sW[2 * SW_SPL + k * SW_STR + f * 8] = *(const float4*)&g_W3[gi];
        }
        __syncthreads();
#pragma unroll
        for (int ks = 0; ks < 4; ks++) {
            unsigned bfr[3][2][2];
            int kr = ks * 16 + (lane & 15);
#pragma unroll
            for (int spl = 0; spl < 3; spl++)
#pragma unroll
                for (int nt = 0; nt < 2; nt++)
                    ldmB2T(bfr[spl][nt], (unsigned)__cvta_generic_to_shared(
                        &sW[spl * SW_SPL + kr * SW_STR + w * 16 + nt * 8]));
            int am = lane & 15, ac = ks * 16 + ((lane >> 4) << 3);
#pragma unroll
            for (int mt = 0; mt < 4; mt++) {
                unsigned afr[3][4];
#pragma unroll
                for (int spl = 0; spl < 3; spl++)
                    ldmA4(afr[spl], (unsigned)__cvta_generic_to_shared(
                        &sA[spl * SA_SPL + (mt * 16 + am) * SA_STR + ac]));
#pragma unroll
                for (int nt = 0; nt < 2; nt++) {
                    float* d = acc[mt][nt];
                    mma16816(d, afr[0], bfr[0][nt]);
                    mma16816(d, afr[0], bfr[1][nt]);
                    mma16816(d, afr[1], bfr[0][nt]);
                    mma16816(d, afr[0], bfr[2][nt]);
                    mma16816(d, afr[1], bfr[1][nt]);
                    mma16816(d, afr[2], bfr[0][nt]);
                }
            }
        }
        __syncthreads();
    }
    int g = lane >> 2, c2 = (lane & 3) * 2;
#pragma unroll
    for (int mt = 0; mt < 4; mt++)
#pragma unroll
        for (int nt = 0; nt < 2; nt++) {
            int col = n0 + w * 16 + nt * 8 + c2;
            float b0 = bias[col], b1 = bias[col + 1];
            int r0 = mt * 16 + g, r1 = r0 + 8;
            g_t[(size_t)r0 * V + col]     = acc[mt][nt][0] + b0;
            g_t[(size_t)r0 * V + col + 1] = acc[mt][nt][1] + b1;
            g_t[(size_t)r1 * V + col]     = acc[mt][nt][2] + b0;
            g_t[(size_t)r1 * V + col + 1] = acc[mt][nt][3] + b1;
        }
}

__global__ void k_softmax(float* __restrict__ out, int step, int steps,
                          const int* __restrict__ tptr)
{
    int b = blockIdx.x, t = threadIdx.x;
    int tb = *tptr;
    float temp = (tb >= 1 && tb < 100000) ? (float)tb : __int_as_float(tb);
    float inv = 1.0f / temp;
    const float* lg = g_t + (size_t)b * V;
    const float* gg = g_g + (size_t)b * V;
    __shared__ float smx[256]; __shared__ int sai[256]; __shared__ float ssum[256];
    float mx = -1e30f; int ai = 0;
    for (int v = t; v < V; v += 256) {
        float x = (lg[v] + gg[v]) * inv;
        if (x > mx) { mx = x; ai = v; }
    }
    smx[t] = mx; sai[t] = ai;
    __syncthreads();
    for (int o = 128; o > 0; o >>= 1) {
        if (t < o) {
            if (smx[t + o] > smx[t] ||
                (smx[t + o] == smx[t] && sai[t + o] < sai[t])) {
                smx[t] = smx[t + o]; sai[t] = sai[t + o];
            }
        }
        __syncthreads();
    }
    float rowmax = smx[0];
    if (t == 0) g_prev[b] = sai[0];
    float s = 0.f;
    for (int v = t; v < V; v += 256) s += expf((lg[v] + gg[v]) * inv - rowmax);
    ssum[t] = s;
    __syncthreads();
    for (int o = 128; o > 0; o >>= 1) {
        if (t < o) ssum[t] += ssum[t + o];
        __syncthreads();
    }
    float rinv = 1.0f / ssum[0];
    float* op = out + ((size_t)b * steps + step) * V;
    for (int v = t; v < V; v += 256)
        op[v] = expf((lg[v] + gg[v]) * inv - rowmax) * rinv;
}

extern "C" void kernel_launch(void* const* d_in, const int* in_sizes, int n_in,
                              void* d_out, int out_size)
{
    const float* z     = (const float*)d_in[0];
    const float* w_z2m = (const float*)d_in[1];
    const float* b_z2m = (const float*)d_in[2];
    const float* bn1_g = (const float*)d_in[3];
    const float* bn1_b = (const float*)d_in[4];
    const float* emb   = (const float*)d_in[5];
    const float* bn2_g = (const float*)d_in[6];
    const float* bn2_b = (const float*)d_in[7];
    const float* w_in  = (const float*)d_in[8];
    const float* b_in  = (const float*)d_in[9];
    const float* w_q   = (const float*)d_in[10];
    const float* w_k   = (const float*)d_in[11];
    const float* w_v   = (const float*)d_in[12];
    const float* w_m1  = (const float*)d_in[13];
    const float* b_m1  = (const float*)d_in[14];
    const float* w_m2  = (const float*)d_in[15];
    const float* b_m2  = (const float*)d_in[16];
    const float* w_gx  = (const float*)d_in[17];
    const float* b_gx  = (const float*)d_in[18];
    const float* w_gm  = (const float*)d_in[19];
    const float* w_m2o = (const float*)d_in[20];
    const float* b_m2o = (const float*)d_in[21];
    const int*   tptr  = (const int*)d_in[23];
    float* out = (float*)d_out;
    int steps = out_size / (B * V);

    cudaFuncSetAttribute(k_logits_mma,
                         cudaFuncAttributeMaxDynamicSharedMemorySize, SMEMB);

    k_init<<<512, 256>>>();
    k_wsplit<<<(int)(((size_t)KV * V / 4 + 255) / 256), 256>>>(w_m2o);
    k_zpre<<<B, 128>>>(z, w_z2m, b_z2m);
    k_bn1<<<4, 128>>>(bn1_g, bn1_b);

    for (int s = 0; s < steps; s++) {
        unsigned fk0, fk1;
        tf2x32(0u, 42u, 0u, (unsigned)s, &fk0, &fk1);
        int ping = s & 1;

        k_embed_bn<<<8, 128>>>(emb, bn2_g, bn2_b);
        k_inp<<<B, 128>>>(w_in, b_in);
        k_qkv<<<dim3(B, 14), 128>>>(ping, w_q, w_k, w_v);
        k_attn<<<dim3(B, NH), 256>>>();
        k_mlp1<<<dim3(B, MM), 128>>>(ping, w_m1, b_m1);
        k_mlp2g<<<dim3(B, MM), 128>>>(ping, w_m2, b_m2, w_gx, b_gx, w_gm);
        k_gumbel<<<(B * V + 255) / 256, 256>>>(fk0, fk1);
        k_logits_mma<<<V / NT, 256, SMEMB>>>(b_m2o);
        k_softmax<<<B, 256>>>(out, s, steps, tptr);
    }
}

// round 16
// speedup vs baseline: 1.3530x; 1.2671x over previous
#include <cuda_runtime.h>
#include <cuda_bf16.h>
#include <stdint.h>
#include <stddef.h>

#define B 64
#define NOISE 128
#define HS 64
#define NH 8
#define MM 4
#define V 32000
#define H 512
#define SI 1024
#define SOS 31999
#define EPS 1e-5f
#define KV 2048
#define NT 128
#define KCH 32
#define NCHUNK (KV/KCH)
#define SA_STR 40
#define SW_STR 136
#define SA_SPL (64*SA_STR)
#define SW_SPL (KCH*SW_STR)
#define BUFE (3*SA_SPL + 3*SW_SPL)
#define SMEMB (2*BUFE*2)

__device__ float g_zpre[B*H];
__device__ float g_zh[B*H];
__device__ float g_s[B*SI];
__device__ float g_inp[B*H];
__device__ float g_q[B*MM*H];
__device__ float g_k[B*5*H];
__device__ float g_v[B*5*H];
__device__ float g_ao[B*MM*H];
__device__ float g_h1[B*MM*H];
__device__ float g_nm[B*MM*H];
__device__ float g_memA[B*MM*H];
__device__ float g_memB[B*MM*H];
__device__ float g_t[B*V];
__device__ int g_prev[B];
__device__ __nv_bfloat16 g_As[3*B*KV];
__device__ __nv_bfloat16 g_W1[(size_t)KV*V];
__device__ __nv_bfloat16 g_W2[(size_t)KV*V];
__device__ __nv_bfloat16 g_W3[(size_t)KV*V];

static __host__ __device__ __forceinline__
void tf2x32(uint32_t k0, uint32_t k1, uint32_t x0, uint32_t x1,
            uint32_t* o0, uint32_t* o1)
{
    uint32_t ks0 = k0, ks1 = k1, ks2 = k0 ^ k1 ^ 0x1BD11BDAu;
    x0 += ks0; x1 += ks1;
#define TFR(r) { x0 += x1; x1 = (x1 << (r)) | (x1 >> (32 - (r))); x1 ^= x0; }
    TFR(13) TFR(15) TFR(26) TFR(6)   x0 += ks1; x1 += ks2 + 1u;
    TFR(17) TFR(29) TFR(16) TFR(24)  x0 += ks2; x1 += ks0 + 2u;
    TFR(13) TFR(15) TFR(26) TFR(6)   x0 += ks0; x1 += ks1 + 3u;
    TFR(17) TFR(29) TFR(16) TFR(24)  x0 += ks1; x1 += ks2 + 4u;
    TFR(13) TFR(15) TFR(26) TFR(6)   x0 += ks2; x1 += ks0 + 5u;
#undef TFR
    *o0 = x0; *o1 = x1;
}

__device__ __forceinline__ float gumbel_from_bits(uint32_t bits)
{
    float f = __uint_as_float((bits >> 9) | 0x3f800000u) - 1.0f;
    const float tiny = 1.17549435e-38f;
    float u = fmaxf(tiny, f + tiny);
    return -logf(-logf(u));
}

__device__ __forceinline__ float lrelu(float x) { return x > 0.0f ? x : 0.2f * x; }

__global__ void k_init()
{
    int t = blockIdx.x * blockDim.x + threadIdx.x;
    if (t < B) g_prev[t] = SOS;
    int stride = gridDim.x * blockDim.x;
    for (int i = t; i < B * MM * H; i += stride) {
        int h = i % H;
        int m = (i / H) % MM;
        g_memA[i] = (h == m) ? 1.0f : 0.0f;
    }
}

// 3-way bf16 split of W, layout [k][v] (row-major, same as input)
__global__ void k_wsplit(const float* __restrict__ W)
{
    size_t i = ((size_t)blockIdx.x * 256 + threadIdx.x) * 4;
    if (i >= (size_t)KV * V) return;
    float4 w4 = *(const float4*)(W + i);
    float x[4] = {w4.x, w4.y, w4.z, w4.w};
    __nv_bfloat16 h1[4], h2[4], h3[4];
#pragma unroll
    for (int u = 0; u < 4; u++) {
        __nv_bfloat16 a = __float2bfloat16(x[u]);
        float r = x[u] - __bfloat162float(a);
        __nv_bfloat16 b = __float2bfloat16(r);
        h1[u] = a; h2[u] = b;
        h3[u] = __float2bfloat16(r - __bfloat162float(b));
    }
    *(uint64_t*)&g_W1[i] = *(uint64_t*)h1;
    *(uint64_t*)&g_W2[i] = *(uint64_t*)h2;
    *(uint64_t*)&g_W3[i] = *(uint64_t*)h3;
}

__global__ void k_zpre(const float* __restrict__ z, const float* __restrict__ w,
                       const float* __restrict__ bias)
{
    __shared__ float sz[NOISE];
    int b = blockIdx.x, t = threadIdx.x;
    if (t < NOISE) sz[t] = z[b * NOISE + t];
    __syncthreads();
    int h4 = t * 4;
    float4 acc = *(const float4*)(bias + h4);
    for (int k = 0; k < NOISE; k++) {
        float s = sz[k];
        float4 w4 = *(const float4*)(w + k * H + h4);
        acc.x = fmaf(s, w4.x, acc.x); acc.y = fmaf(s, w4.y, acc.y);
        acc.z = fmaf(s, w4.z, acc.z); acc.w = fmaf(s, w4.w, acc.w);
    }
    float* dst = g_zpre + b * H + h4;
    dst[0] = lrelu(acc.x); dst[1] = lrelu(acc.y);
    dst[2] = lrelu(acc.z); dst[3] = lrelu(acc.w);
}

// column-per-block BN: grid(H), block(64)
__global__ void k_bn1(const float* __restrict__ g, const float* __restrict__ bb)
{
    int c = blockIdx.x, b = threadIdx.x;
    __shared__ float red[64];
    float x = g_zpre[b * H + c];
    red[b] = x; __syncthreads();
    for (int o = 32; o > 0; o >>= 1) { if (b < o) red[b] += red[b + o]; __syncthreads(); }
    float mu = red[0] * (1.0f / B);
    __syncthreads();
    float d = x - mu;
    red[b] = d * d; __syncthreads();
    for (int o = 32; o > 0; o >>= 1) { if (b < o) red[b] += red[b + o]; __syncthreads(); }
    float var = red[0] * (1.0f / B);
    g_zh[b * H + c] = g[c] * (x - mu) * rsqrtf(var + EPS) + bb[c];
}

__device__ __forceinline__ float sval(const float* __restrict__ emb, int c, int b)
{
    if (c < H) return lrelu(emb[(size_t)g_prev[b] * H + c]);
    return g_zh[b * H + c - H];
}

// grid(SI), block(64)
__global__ void k_embed_bn(const float* __restrict__ emb,
                           const float* __restrict__ g2, const float* __restrict__ b2)
{
    int c = blockIdx.x, b = threadIdx.x;
    __shared__ float red[64];
    float x = sval(emb, c, b);
    red[b] = x; __syncthreads();
    for (int o = 32; o > 0; o >>= 1) { if (b < o) red[b] += red[b + o]; __syncthreads(); }
    float mu = red[0] * (1.0f / B);
    __syncthreads();
    float d = x - mu;
    red[b] = d * d; __syncthreads();
    for (int o = 32; o > 0; o >>= 1) { if (b < o) red[b] += red[b + o]; __syncthreads(); }
    float var = red[0] * (1.0f / B);
    g_s[b * SI + c] = g2[c] * (x - mu) * rsqrtf(var + EPS) + b2[c];
}

__global__ void k_inp(const float* __restrict__ w, const float* __restrict__ bias)
{
    __shared__ float ss[SI];
    int b = blockIdx.x, t = threadIdx.x;
    for (int i = t; i < SI; i += 128) ss[i] = g_s[b * SI + i];
    __syncthreads();
    int h4 = t * 4;
    float4 acc = *(const float4*)(bias + h4);
    for (int k = 0; k < SI; k++) {
        float s = ss[k];
        float4 w4 = *(const float4*)(w + k * H + h4);
        acc.x = fmaf(s, w4.x, acc.x); acc.y = fmaf(s, w4.y, acc.y);
        acc.z = fmaf(s, w4.z, acc.z); acc.w = fmaf(s, w4.w, acc.w);
    }
    *(float4*)(g_inp + b * H + h4) = acc;
}

__global__ void k_qkv(int ping, const float* __restrict__ wq,
                      const float* __restrict__ wk, const float* __restrict__ wv)
{
    const float* memIn = ping ? g_memB : g_memA;
    int b = blockIdx.x, j = blockIdx.y, t = threadIdx.x;
    const float* src; const float* W; float* dst;
    if (j < 4) {
        src = memIn + (b * MM + j) * H; W = wq; dst = g_q + (b * MM + j) * H;
    } else if (j < 9) {
        int n = j - 4;
        src = (n < 4) ? (memIn + (b * MM + n) * H) : (g_inp + b * H);
        W = wk; dst = g_k + (b * 5 + n) * H;
    } else {
        int n = j - 9;
        src = (n < 4) ? (memIn + (b * MM + n) * H) : (g_inp + b * H);
        W = wv; dst = g_v + (b * 5 + n) * H;
    }
    __shared__ float ss[H];
    for (int i = t; i < H; i += 128) ss[i] = src[i];
    __syncthreads();
    int h4 = t * 4;
    float4 acc = make_float4(0.f, 0.f, 0.f, 0.f);
    for (int k = 0; k < H; k++) {
        float s = ss[k];
        float4 w4 = *(const float4*)(W + k * H + h4);
        acc.x = fmaf(s, w4.x, acc.x); acc.y = fmaf(s, w4.y, acc.y);
        acc.z = fmaf(s, w4.z, acc.z); acc.w = fmaf(s, w4.w, acc.w);
    }
    *(float4*)(dst + h4) = acc;
}

__global__ void k_attn()
{
    int b = blockIdx.x, hd = blockIdx.y, t = threadIdx.x;
    __shared__ float qs[4][HS], ks[5][HS], vs[5][HS], att[4][5];
    int m = t >> 6, d = t & 63;
    qs[m][d] = g_q[(b * MM + m) * H + hd * HS + d];
    ks[m][d] = g_k[(b * 5 + m) * H + hd * HS + d];
    vs[m][d] = g_v[(b * 5 + m) * H + hd * HS + d];
    if (t < 64) {
        ks[4][t] = g_k[(b * 5 + 4) * H + hd * HS + t];
        vs[4][t] = g_v[(b * 5 + 4) * H + hd * HS + t];
    }
    __syncthreads();
    if (t < 20) {
        int mm = t / 5, nn = t % 5;
        float s = 0.f;
        for (int i = 0; i < HS; i++) s += qs[mm][i] * ks[nn][i];
        att[mm][nn] = s * 0.125f;
    }
    __syncthreads();
    if (t < 4) {
        float mx = att[t][0];
        for (int n = 1; n < 5; n++) mx = fmaxf(mx, att[t][n]);
        float e[5], sum = 0.f;
        for (int n = 0; n < 5; n++) { e[n] = expf(att[t][n] - mx); sum += e[n]; }
        for (int n = 0; n < 5; n++) att[t][n] = e[n] / sum;
    }
    __syncthreads();
    float acc = 0.f;
    for (int n = 0; n < 5; n++) acc += att[m][n] * vs[n][d];
    g_ao[(b * MM + m) * H + hd * HS + d] = acc;
}

__global__ void k_mlp1(int ping, const float* __restrict__ w, const float* __restrict__ bias)
{
    const float* memIn = ping ? g_memB : g_memA;
    int b = blockIdx.x, m = blockIdx.y, t = threadIdx.x;
    __shared__ float ss[H];
    int base = (b * MM + m) * H;
    for (int i = t; i < H; i += 128) {
        float v = memIn[base + i] + g_ao[base + i];
        ss[i] = v; g_nm[base + i] = v;
    }
    __syncthreads();
    int h4 = t * 4;
    float4 acc = *(const float4*)(bias + h4);
    for (int k = 0; k < H; k++) {
        float s = ss[k];
        float4 w4 = *(const float4*)(w + k * H + h4);
        acc.x = fmaf(s, w4.x, acc.x); acc.y = fmaf(s, w4.y, acc.y);
        acc.z = fmaf(s, w4.z, acc.z); acc.w = fmaf(s, w4.w, acc.w);
    }
    float* dst = g_h1 + base + h4;
    dst[0] = lrelu(acc.x); dst[1] = lrelu(acc.y);
    dst[2] = lrelu(acc.z); dst[3] = lrelu(acc.w);
}

__global__ void k_mlp2g(int ping, const float* __restrict__ w, const float* __restrict__ bias,
                        const float* __restrict__ w_gx, const float* __restrict__ b_gx,
                        const float* __restrict__ w_gm)
{
    const float* memIn = ping ? g_memB : g_memA;
    float*      memOut = ping ? g_memA : g_memB;
    int b = blockIdx.x, m = blockIdx.y, t = threadIdx.x;
    __shared__ float h1s[H];
    __shared__ float red[128][4];
    __shared__ float ig_s, fg_s;
    int base = (b * MM + m) * H;
    for (int i = t; i < H; i += 128) h1s[i] = g_h1[base + i];
    float p0 = 0.f, p1 = 0.f, p2 = 0.f, p3 = 0.f;
    for (int k = t; k < H; k += 128) {
        float tm = tanhf(memIn[base + k]);
        p0 = fmaf(tm, w_gm[k * 2 + 0], p0);
        p1 = fmaf(tm, w_gm[k * 2 + 1], p1);
        float iv = g_inp[b * H + k];
        p2 = fmaf(iv, w_gx[k * 2 + 0], p2);
        p3 = fmaf(iv, w_gx[k * 2 + 1], p3);
    }
    red[t][0] = p0; red[t][1] = p1; red[t][2] = p2; red[t][3] = p3;
    __syncthreads();
    if (t == 0) {
        float s0 = 0.f, s1 = 0.f, s2 = 0.f, s3 = 0.f;
        for (int i = 0; i < 128; i++) {
            s0 += red[i][0]; s1 += red[i][1]; s2 += red[i][2]; s3 += red[i][3];
        }
        float g0 = s2 + b_gx[0] + s0;
        float g1 = s3 + b_gx[1] + s1 + 1.0f;
        ig_s = 1.f / (1.f + expf(-g0));
        fg_s = 1.f / (1.f + expf(-g1));
    }
    __syncthreads();
    int h4 = t * 4;
    float4 acc = *(const float4*)(bias + h4);
    for (int k = 0; k < H; k++) {
        float s = h1s[k];
        float4 w4 = *(const float4*)(w + k * H + h4);
        acc.x = fmaf(s, w4.x, acc.x); acc.y = fmaf(s, w4.y, acc.y);
        acc.z = fmaf(s, w4.z, acc.z); acc.w = fmaf(s, w4.w, acc.w);
    }
    float ig = ig_s, fg = fg_s;
    float a4[4] = {acc.x, acc.y, acc.z, acc.w};
#pragma unroll
    for (int u = 0; u < 4; u++) {
        int h = h4 + u;
        float nm2 = g_nm[base + h] + a4[u];
        float nv = fg * memIn[base + h] + ig * tanhf(nm2);
        memOut[base + h] = nv;
        __nv_bfloat16 s1b = __float2bfloat16(nv);
        float r = nv - __bfloat162float(s1b);
        __nv_bfloat16 s2b = __float2bfloat16(r);
        float r2 = r - __bfloat162float(s2b);
        int kk = m * H + h;
        g_As[(size_t)b * KV + kk]           = s1b;
        g_As[(size_t)(B + b) * KV + kk]     = s2b;
        g_As[(size_t)(2 * B + b) * KV + kk] = __float2bfloat16(r2);
    }
}

__device__ __forceinline__ void mma16816(float* d, const unsigned* a, const unsigned* b)
{
    asm volatile("mma.sync.aligned.m16n8k16.row.col.f32.bf16.bf16.f32 "
        "{%0,%1,%2,%3},{%4,%5,%6,%7},{%8,%9},{%0,%1,%2,%3};"
        : "+f"(d[0]), "+f"(d[1]), "+f"(d[2]), "+f"(d[3])
        : "r"(a[0]), "r"(a[1]), "r"(a[2]), "r"(a[3]), "r"(b[0]), "r"(b[1]));
}
__device__ __forceinline__ void ldmA4(unsigned* r, unsigned a)
{
    asm volatile("ldmatrix.sync.aligned.m8n8.x4.shared.b16 {%0,%1,%2,%3},[%4];"
        : "=r"(r[0]), "=r"(r[1]), "=r"(r[2]), "=r"(r[3]) : "r"(a));
}
__device__ __forceinline__ void ldmB2T(unsigned* r, unsigned a)
{
    asm volatile("ldmatrix.sync.aligned.m8n8.x2.trans.shared.b16 {%0,%1},[%2];"
        : "=r"(r[0]), "=r"(r[1]) : "r"(a));
}
__device__ __forceinline__ void cpa16(unsigned dst, const void* src)
{ asm volatile("cp.async.cg.shared.global [%0], [%1], 16;" :: "r"(dst), "l"(src)); }

extern __shared__ __nv_bfloat16 s_dyn[];

__global__ void __launch_bounds__(256) k_logits_mma(const float* __restrict__ bias,
                                                    unsigned fk0, unsigned fk1)
{
    int t = threadIdx.x, w = t >> 5, lane = t & 31;
    int n0 = blockIdx.x * NT;
    unsigned sb = (unsigned)__cvta_generic_to_shared(s_dyn);
    const __nv_bfloat16* Wp[3] = {g_W1, g_W2, g_W3};
    float acc[4][2][4];
#pragma unroll
    for (int i = 0; i < 4; i++)
#pragma unroll
        for (int j = 0; j < 2; j++)
#pragma unroll
            for (int q = 0; q < 4; q++) acc[i][j][q] = 0.f;

    // issue chunk 0
    {
        int kt = 0;
        unsigned base = sb;
        for (int e = t; e < 768; e += 256) {
            int spl = e >> 8, m = (e >> 2) & 63, f = e & 3;
            cpa16(base + (spl * SA_SPL + m * SA_STR + f * 8) * 2,
                  &g_As[(size_t)(spl * B + m) * KV + kt + f * 8]);
        }
        for (int e = t; e < 1536; e += 256) {
            int spl = e >> 9, k = (e >> 4) & 31, f = e & 15;
            cpa16(base + (3 * SA_SPL + spl * SW_SPL + k * SW_STR + f * 8) * 2,
                  &Wp[spl][(size_t)(kt + k) * V + n0 + f * 8]);
        }
        asm volatile("cp.async.commit_group;");
    }

    for (int ch = 0; ch < NCHUNK; ch++) {
        if (ch + 1 < NCHUNK) {   // issue next chunk into other buffer
            int kt = (ch + 1) * KCH;
            unsigned base = sb + ((ch + 1) & 1) * BUFE * 2;
            for (int e = t; e < 768; e += 256) {
                int spl = e >> 8, m = (e >> 2) & 63, f = e & 3;
                cpa16(base + (spl * SA_SPL + m * SA_STR + f * 8) * 2,
                      &g_As[(size_t)(spl * B + m) * KV + kt + f * 8]);
            }
            for (int e = t; e < 1536; e += 256) {
                int spl = e >> 9, k = (e >> 4) & 31, f = e & 15;
                cpa16(base + (3 * SA_SPL + spl * SW_SPL + k * SW_STR + f * 8) * 2,
                      &Wp[spl][(size_t)(kt + k) * V + n0 + f * 8]);
            }
            asm volatile("cp.async.commit_group;");
            asm volatile("cp.async.wait_group 1;");
        } else {
            asm volatile("cp.async.wait_group 0;");
        }
        __syncthreads();
        __nv_bfloat16* sA = s_dyn + (ch & 1) * BUFE;
        __nv_bfloat16* sW = sA + 3 * SA_SPL;
#pragma unroll
        for (int ks = 0; ks < 2; ks++) {
            unsigned bfr[3][2][2];
            int kr = ks * 16 + (lane & 15);
#pragma unroll
            for (int spl = 0; spl < 3; spl++)
#pragma unroll
                for (int nt = 0; nt < 2; nt++)
                    ldmB2T(bfr[spl][nt], (unsigned)__cvta_generic_to_shared(
                        &sW[spl * SW_SPL + kr * SW_STR + w * 16 + nt * 8]));
            int am = lane & 15, ac = ks * 16 + ((lane >> 4) << 3);
#pragma unroll
            for (int mt = 0; mt < 4; mt++) {
                unsigned afr[3][4];
#pragma unroll
                for (int spl = 0; spl < 3; spl++)
                    ldmA4(afr[spl], (unsigned)__cvta_generic_to_shared(
                        &sA[spl * SA_SPL + (mt * 16 + am) * SA_STR + ac]));
#pragma unroll
                for (int nt = 0; nt < 2; nt++) {
                    float* d = acc[mt][nt];
                    mma16816(d, afr[0], bfr[0][nt]);
                    mma16816(d, afr[0], bfr[1][nt]);
                    mma16816(d, afr[1], bfr[0][nt]);
                    mma16816(d, afr[0], bfr[2][nt]);
                    mma16816(d, afr[1], bfr[1][nt]);
                    mma16816(d, afr[2], bfr[0][nt]);
                }
            }
        }
        __syncthreads();
    }
    // epilogue: bias + fused gumbel; g_t = logits + bias + gumbel
    int g = lane >> 2, c2 = (lane & 3) * 2;
#pragma unroll
    for (int mt = 0; mt < 4; mt++)
#pragma unroll
        for (int nt = 0; nt < 2; nt++) {
            int col = n0 + w * 16 + nt * 8 + c2;
            float b0 = bias[col], b1 = bias[col + 1];
            int r0 = mt * 16 + g, r1 = r0 + 8;
            unsigned o0, o1;
            unsigned j00 = (unsigned)(r0 * V + col);
            tf2x32(fk0, fk1, 0u, j00, &o0, &o1);
            float g00 = gumbel_from_bits(o0 ^ o1);
            tf2x32(fk0, fk1, 0u, j00 + 1u, &o0, &o1);
            float g01 = gumbel_from_bits(o0 ^ o1);
            unsigned j10 = (unsigned)(r1 * V + col);
            tf2x32(fk0, fk1, 0u, j10, &o0, &o1);
            float g10 = gumbel_from_bits(o0 ^ o1);
            tf2x32(fk0, fk1, 0u, j10 + 1u, &o0, &o1);
            float g11 = gumbel_from_bits(o0 ^ o1);
            g_t[(size_t)r0 * V + col]     = acc[mt][nt][0] + b0 + g00;
            g_t[(size_t)r0 * V + col + 1] = acc[mt][nt][1] + b1 + g01;
            g_t[(size_t)r1 * V + col]     = acc[mt][nt][2] + b0 + g10;
            g_t[(size_t)r1 * V + col + 1] = acc[mt][nt][3] + b1 + g11;
        }
}

__global__ void k_softmax(float* __restrict__ out, int step, int steps,
                          const int* __restrict__ tptr)
{
    int b = blockIdx.x, t = threadIdx.x;
    int tb = *tptr;
    float temp = (tb >= 1 && tb < 100000) ? (float)tb : __int_as_float(tb);
    float inv = 1.0f / temp;
    const float* lg = g_t + (size_t)b * V;
    __shared__ float smx[256]; __shared__ int sai[256]; __shared__ float ssum[256];
    float mx = -1e30f; int ai = 0;
    for (int v = t; v < V; v += 256) {
        float x = lg[v] * inv;
        if (x > mx) { mx = x; ai = v; }
    }
    smx[t] = mx; sai[t] = ai;
    __syncthreads();
    for (int o = 128; o > 0; o >>= 1) {
        if (t < o) {
            if (smx[t + o] > smx[t] ||
                (smx[t + o] == smx[t] && sai[t + o] < sai[t])) {
                smx[t] = smx[t + o]; sai[t] = sai[t + o];
            }
        }
        __syncthreads();
    }
    float rowmax = smx[0];
    if (t == 0) g_prev[b] = sai[0];
    float s = 0.f;
    for (int v = t; v < V; v += 256) s += expf(lg[v] * inv - rowmax);
    ssum[t] = s;
    __syncthreads();
    for (int o = 128; o > 0; o >>= 1) {
        if (t < o) ssum[t] += ssum[t + o];
        __syncthreads();
    }
    float rinv = 1.0f / ssum[0];
    float* op = out + ((size_t)b * steps + step) * V;
    for (int v = t; v < V; v += 256)
        op[v] = expf(lg[v] * inv - rowmax) * rinv;
}

extern "C" void kernel_launch(void* const* d_in, const int* in_sizes, int n_in,
                              void* d_out, int out_size)
{
    const float* z     = (const float*)d_in[0];
    const float* w_z2m = (const float*)d_in[1];
    const float* b_z2m = (const float*)d_in[2];
    const float* bn1_g = (const float*)d_in[3];
    const float* bn1_b = (const float*)d_in[4];
    const float* emb   = (const float*)d_in[5];
    const float* bn2_g = (const float*)d_in[6];
    const float* bn2_b = (const float*)d_in[7];
    const float* w_in  = (const float*)d_in[8];
    const float* b_in  = (const float*)d_in[9];
    const float* w_q   = (const float*)d_in[10];
    const float* w_k   = (const float*)d_in[11];
    const float* w_v   = (const float*)d_in[12];
    const float* w_m1  = (const float*)d_in[13];
    const float* b_m1  = (const float*)d_in[14];
    const float* w_m2  = (const float*)d_in[15];
    const float* b_m2  = (const float*)d_in[16];
    const float* w_gx  = (const float*)d_in[17];
    const float* b_gx  = (const float*)d_in[18];
    const float* w_gm  = (const float*)d_in[19];
    const float* w_m2o = (const float*)d_in[20];
    const float* b_m2o = (const float*)d_in[21];
    const int*   tptr  = (const int*)d_in[23];
    float* out = (float*)d_out;
    int steps = out_size / (B * V);

    cudaFuncSetAttribute(k_logits_mma,
                         cudaFuncAttributeMaxDynamicSharedMemorySize, SMEMB);

    k_init<<<512, 256>>>();
    k_wsplit<<<64000, 256>>>(w_m2o);
    k_zpre<<<B, 128>>>(z, w_z2m, b_z2m);
    k_bn1<<<H, 64>>>(bn1_g, bn1_b);

    for (int s = 0; s < steps; s++) {
        unsigned fk0, fk1;
        tf2x32(0u, 42u, 0u, (unsigned)s, &fk0, &fk1);
        int ping = s & 1;

        k_embed_bn<<<SI, 64>>>(emb, bn2_g, bn2_b);
        k_inp<<<B, 128>>>(w_in, b_in);
        k_qkv<<<dim3(B, 14), 128>>>(ping, w_q, w_k, w_v);
        k_attn<<<dim3(B, NH), 256>>>();
        k_mlp1<<<dim3(B, MM), 128>>>(ping, w_m1, b_m1);
        k_mlp2g<<<dim3(B, MM), 128>>>(ping, w_m2, b_m2, w_gx, b_gx, w_gm);
        k_logits_mma<<<V / NT, 256, SMEMB>>>(b_m2o, fk0, fk1);
        k_softmax<<<B, 256>>>(out, s, steps, tptr);
    }
}

// round 17
// speedup vs baseline: 1.5474x; 1.1437x over previous
#include <cuda_runtime.h>
#include <cuda_bf16.h>
#include <stdint.h>
#include <stddef.h>

#define B 64
#define NOISE 128
#define HS 64
#define NH 8
#define MM 4
#define V 32000
#define H 512
#define SI 1024
#define SOS 31999
#define EPS 1e-5f
#define KV 2048
#define NT 128
#define KCH 32
#define NCHUNK (KV/KCH)
#define SA_STR 40
#define SW_STR 136
#define SA_SPL (64*SA_STR)
#define SW_SPL (KCH*SW_STR)
#define BUFE (2*SA_SPL + 2*SW_SPL)
#define SMEMB (2*BUFE*2)

__device__ float g_zpre[B*H];
__device__ float g_zh[B*H];
__device__ float g_s[B*SI];
__device__ float g_inp[B*H];
__device__ float g_q[B*MM*H];
__device__ float g_k[B*5*H];
__device__ float g_v[B*5*H];
__device__ float g_ao[B*MM*H];
__device__ float g_h1[B*MM*H];
__device__ float g_nm[B*MM*H];
__device__ float g_memA[B*MM*H];
__device__ float g_memB[B*MM*H];
__device__ float g_t[B*V];
__device__ int g_prev[B];
__device__ __nv_bfloat16 g_As[2*B*KV];
__device__ __nv_bfloat16 g_W1[(size_t)KV*V];
__device__ __nv_bfloat16 g_W2[(size_t)KV*V];

static __host__ __device__ __forceinline__
void tf2x32(uint32_t k0, uint32_t k1, uint32_t x0, uint32_t x1,
            uint32_t* o0, uint32_t* o1)
{
    uint32_t ks0 = k0, ks1 = k1, ks2 = k0 ^ k1 ^ 0x1BD11BDAu;
    x0 += ks0; x1 += ks1;
#define TFR(r) { x0 += x1; x1 = (x1 << (r)) | (x1 >> (32 - (r))); x1 ^= x0; }
    TFR(13) TFR(15) TFR(26) TFR(6)   x0 += ks1; x1 += ks2 + 1u;
    TFR(17) TFR(29) TFR(16) TFR(24)  x0 += ks2; x1 += ks0 + 2u;
    TFR(13) TFR(15) TFR(26) TFR(6)   x0 += ks0; x1 += ks1 + 3u;
    TFR(17) TFR(29) TFR(16) TFR(24)  x0 += ks1; x1 += ks2 + 4u;
    TFR(13) TFR(15) TFR(26) TFR(6)   x0 += ks2; x1 += ks0 + 5u;
#undef TFR
    *o0 = x0; *o1 = x1;
}

__device__ __forceinline__ float gumbel_from_bits(uint32_t bits)
{
    float f = __uint_as_float((bits >> 9) | 0x3f800000u) - 1.0f;
    const float tiny = 1.17549435e-38f;
    float u = fmaxf(tiny, f + tiny);
    return -logf(-logf(u));
}

__device__ __forceinline__ float lrelu(float x) { return x > 0.0f ? x : 0.2f * x; }

__global__ void k_init()
{
    int t = blockIdx.x * blockDim.x + threadIdx.x;
    if (t < B) g_prev[t] = SOS;
    int stride = gridDim.x * blockDim.x;
    for (int i = t; i < B * MM * H; i += stride) {
        int h = i % H;
        int m = (i / H) % MM;
        g_memA[i] = (h == m) ? 1.0f : 0.0f;
    }
}

// 2-way bf16 split of W, layout [k][v]
__global__ void k_wsplit(const float* __restrict__ W)
{
    size_t i = ((size_t)blockIdx.x * 256 + threadIdx.x) * 4;
    if (i >= (size_t)KV * V) return;
    float4 w4 = *(const float4*)(W + i);
    float x[4] = {w4.x, w4.y, w4.z, w4.w};
    __nv_bfloat16 h1[4], h2[4];
#pragma unroll
    for (int u = 0; u < 4; u++) {
        __nv_bfloat16 a = __float2bfloat16(x[u]);
        h1[u] = a;
        h2[u] = __float2bfloat16(x[u] - __bfloat162float(a));
    }
    *(uint64_t*)&g_W1[i] = *(uint64_t*)h1;
    *(uint64_t*)&g_W2[i] = *(uint64_t*)h2;
}

__global__ void k_zpre(const float* __restrict__ z, const float* __restrict__ w,
                       const float* __restrict__ bias)
{
    __shared__ float sz[NOISE];
    int b = blockIdx.x, t = threadIdx.x;
    if (t < NOISE) sz[t] = z[b * NOISE + t];
    __syncthreads();
    int h4 = t * 4;
    float4 acc = *(const float4*)(bias + h4);
    for (int k = 0; k < NOISE; k++) {
        float s = sz[k];
        float4 w4 = *(const float4*)(w + k * H + h4);
        acc.x = fmaf(s, w4.x, acc.x); acc.y = fmaf(s, w4.y, acc.y);
        acc.z = fmaf(s, w4.z, acc.z); acc.w = fmaf(s, w4.w, acc.w);
    }
    float* dst = g_zpre + b * H + h4;
    dst[0] = lrelu(acc.x); dst[1] = lrelu(acc.y);
    dst[2] = lrelu(acc.z); dst[3] = lrelu(acc.w);
}

__global__ void k_bn1(const float* __restrict__ g, const float* __restrict__ bb)
{
    int c = blockIdx.x, b = threadIdx.x;
    __shared__ float red[64];
    float x = g_zpre[b * H + c];
    red[b] = x; __syncthreads();
    for (int o = 32; o > 0; o >>= 1) { if (b < o) red[b] += red[b + o]; __syncthreads(); }
    float mu = red[0] * (1.0f / B);
    __syncthreads();
    float d = x - mu;
    red[b] = d * d; __syncthreads();
    for (int o = 32; o > 0; o >>= 1) { if (b < o) red[b] += red[b + o]; __syncthreads(); }
    float var = red[0] * (1.0f / B);
    g_zh[b * H + c] = g[c] * (x - mu) * rsqrtf(var + EPS) + bb[c];
}

__device__ __forceinline__ float sval(const float* __restrict__ emb, int c, int b)
{
    if (c < H) return lrelu(emb[(size_t)g_prev[b] * H + c]);
    return g_zh[b * H + c - H];
}

__global__ void k_embed_bn(const float* __restrict__ emb,
                           const float* __restrict__ g2, const float* __restrict__ b2)
{
    int c = blockIdx.x, b = threadIdx.x;
    __shared__ float red[64];
    float x = sval(emb, c, b);
    red[b] = x; __syncthreads();
    for (int o = 32; o > 0; o >>= 1) { if (b < o) red[b] += red[b + o]; __syncthreads(); }
    float mu = red[0] * (1.0f / B);
    __syncthreads();
    float d = x - mu;
    red[b] = d * d; __syncthreads();
    for (int o = 32; o > 0; o >>= 1) { if (b < o) red[b] += red[b + o]; __syncthreads(); }
    float var = red[0] * (1.0f / B);
    g_s[b * SI + c] = g2[c] * (x - mu) * rsqrtf(var + EPS) + b2[c];
}

__global__ void k_inp(const float* __restrict__ w, const float* __restrict__ bias)
{
    __shared__ float ss[SI];
    int b = blockIdx.x, t = threadIdx.x;
    for (int i = t; i < SI; i += 128) ss[i] = g_s[b * SI + i];
    __syncthreads();
    int h4 = t * 4;
    float4 acc = *(const float4*)(bias + h4);
    for (int k = 0; k < SI; k++) {
        float s = ss[k];
        float4 w4 = *(const float4*)(w + k * H + h4);
        acc.x = fmaf(s, w4.x, acc.x); acc.y = fmaf(s, w4.y, acc.y);
        acc.z = fmaf(s, w4.z, acc.z); acc.w = fmaf(s, w4.w, acc.w);
    }
    *(float4*)(g_inp + b * H + h4) = acc;
}

__global__ void k_qkv(int ping, const float* __restrict__ wq,
                      const float* __restrict__ wk, const float* __restrict__ wv)
{
    const float* memIn = ping ? g_memB : g_memA;
    int b = blockIdx.x, j = blockIdx.y, t = threadIdx.x;
    const float* src; const float* W; float* dst;
    if (j < 4) {
        src = memIn + (b * MM + j) * H; W = wq; dst = g_q + (b * MM + j) * H;
    } else if (j < 9) {
        int n = j - 4;
        src = (n < 4) ? (memIn + (b * MM + n) * H) : (g_inp + b * H);
        W = wk; dst = g_k + (b * 5 + n) * H;
    } else {
        int n = j - 9;
        src = (n < 4) ? (memIn + (b * MM + n) * H) : (g_inp + b * H);
        W = wv; dst = g_v + (b * 5 + n) * H;
    }
    __shared__ float ss[H];
    for (int i = t; i < H; i += 128) ss[i] = src[i];
    __syncthreads();
    int h4 = t * 4;
    float4 acc = make_float4(0.f, 0.f, 0.f, 0.f);
    for (int k = 0; k < H; k++) {
        float s = ss[k];
        float4 w4 = *(const float4*)(W + k * H + h4);
        acc.x = fmaf(s, w4.x, acc.x); acc.y = fmaf(s, w4.y, acc.y);
        acc.z = fmaf(s, w4.z, acc.z); acc.w = fmaf(s, w4.w, acc.w);
    }
    *(float4*)(dst + h4) = acc;
}

__global__ void k_attn()
{
    int b = blockIdx.x, hd = blockIdx.y, t = threadIdx.x;
    __shared__ float qs[4][HS], ks[5][HS], vs[5][HS], att[4][5];
    int m = t >> 6, d = t & 63;
    qs[m][d] = g_q[(b * MM + m) * H + hd * HS + d];
    ks[m][d] = g_k[(b * 5 + m) * H + hd * HS + d];
    vs[m][d] = g_v[(b * 5 + m) * H + hd * HS + d];
    if (t < 64) {
        ks[4][t] = g_k[(b * 5 + 4) * H + hd * HS + t];
        vs[4][t] = g_v[(b * 5 + 4) * H + hd * HS + t];
    }
    __syncthreads();
    if (t < 20) {
        int mm = t / 5, nn = t % 5;
        float s = 0.f;
        for (int i = 0; i < HS; i++) s += qs[mm][i] * ks[nn][i];
        att[mm][nn] = s * 0.125f;
    }
    __syncthreads();
    if (t < 4) {
        float mx = att[t][0];
        for (int n = 1; n < 5; n++) mx = fmaxf(mx, att[t][n]);
        float e[5], sum = 0.f;
        for (int n = 0; n < 5; n++) { e[n] = expf(att[t][n] - mx); sum += e[n]; }
        for (int n = 0; n < 5; n++) att[t][n] = e[n] / sum;
    }
    __syncthreads();
    float acc = 0.f;
    for (int n = 0; n < 5; n++) acc += att[m][n] * vs[n][d];
    g_ao[(b * MM + m) * H + hd * HS + d] = acc;
}

__global__ void k_mlp1(int ping, const float* __restrict__ w, const float* __restrict__ bias)
{
    const float* memIn = ping ? g_memB : g_memA;
    int b = blockIdx.x, m = blockIdx.y, t = threadIdx.x;
    __shared__ float ss[H];
    int base = (b * MM + m) * H;
    for (int i = t; i < H; i += 128) {
        float v = memIn[base + i] + g_ao[base + i];
        ss[i] = v; g_nm[base + i] = v;
    }
    __syncthreads();
    int h4 = t * 4;
    float4 acc = *(const float4*)(bias + h4);
    for (int k = 0; k < H; k++) {
        float s = ss[k];
        float4 w4 = *(const float4*)(w + k * H + h4);
        acc.x = fmaf(s, w4.x, acc.x); acc.y = fmaf(s, w4.y, acc.y);
        acc.z = fmaf(s, w4.z, acc.z); acc.w = fmaf(s, w4.w, acc.w);
    }
    float* dst = g_h1 + base + h4;
    dst[0] = lrelu(acc.x); dst[1] = lrelu(acc.y);
    dst[2] = lrelu(acc.z); dst[3] = lrelu(acc.w);
}

__global__ void k_mlp2g(int ping, const float* __restrict__ w, const float* __restrict__ bias,
                        const float* __restrict__ w_gx, const float* __restrict__ b_gx,
                        const float* __restrict__ w_gm)
{
    const float* memIn = ping ? g_memB : g_memA;
    float*      memOut = ping ? g_memA : g_memB;
    int b = blockIdx.x, m = blockIdx.y, t = threadIdx.x;
    __shared__ float h1s[H];
    __shared__ float red[128][4];
    __shared__ float ig_s, fg_s;
    int base = (b * MM + m) * H;
    for (int i = t; i < H; i += 128) h1s[i] = g_h1[base + i];
    float p0 = 0.f, p1 = 0.f, p2 = 0.f, p3 = 0.f;
    for (int k = t; k < H; k += 128) {
        float tm = tanhf(memIn[base + k]);
        p0 = fmaf(tm, w_gm[k * 2 + 0], p0);
        p1 = fmaf(tm, w_gm[k * 2 + 1], p1);
        float iv = g_inp[b * H + k];
        p2 = fmaf(iv, w_gx[k * 2 + 0], p2);
        p3 = fmaf(iv, w_gx[k * 2 + 1], p3);
    }
    red[t][0] = p0; red[t][1] = p1; red[t][2] = p2; red[t][3] = p3;
    __syncthreads();
    if (t == 0) {
        float s0 = 0.f, s1 = 0.f, s2 = 0.f, s3 = 0.f;
        for (int i = 0; i < 128; i++) {
            s0 += red[i][0]; s1 += red[i][1]; s2 += red[i][2]; s3 += red[i][3];
        }
        float g0 = s2 + b_gx[0] + s0;
        float g1 = s3 + b_gx[1] + s1 + 1.0f;
        ig_s = 1.f / (1.f + expf(-g0));
        fg_s = 1.f / (1.f + expf(-g1));
    }
    __syncthreads();
    int h4 = t * 4;
    float4 acc = *(const float4*)(bias + h4);
    for (int k = 0; k < H; k++) {
        float s = h1s[k];
        float4 w4 = *(const float4*)(w + k * H + h4);
        acc.x = fmaf(s, w4.x, acc.x); acc.y = fmaf(s, w4.y, acc.y);
        acc.z = fmaf(s, w4.z, acc.z); acc.w = fmaf(s, w4.w, acc.w);
    }
    float ig = ig_s, fg = fg_s;
    float a4[4] = {acc.x, acc.y, acc.z, acc.w};
#pragma unroll
    for (int u = 0; u < 4; u++) {
        int h = h4 + u;
        float nm2 = g_nm[base + h] + a4[u];
        float nv = fg * memIn[base + h] + ig * tanhf(nm2);
        memOut[base + h] = nv;
        __nv_bfloat16 s1b = __float2bfloat16(nv);
        int kk = m * H + h;
        g_As[(size_t)b * KV + kk]       = s1b;
        g_As[(size_t)(B + b) * KV + kk] = __float2bfloat16(nv - __bfloat162float(s1b));
    }
}

__device__ __forceinline__ void mma16816(float* d, const unsigned* a, const unsigned* b)
{
    asm volatile("mma.sync.aligned.m16n8k16.row.col.f32.bf16.bf16.f32 "
        "{%0,%1,%2,%3},{%4,%5,%6,%7},{%8,%9},{%0,%1,%2,%3};"
        : "+f"(d[0]), "+f"(d[1]), "+f"(d[2]), "+f"(d[3])
        : "r"(a[0]), "r"(a[1]), "r"(a[2]), "r"(a[3]), "r"(b[0]), "r"(b[1]));
}
__device__ __forceinline__ void ldmA4(unsigned* r, unsigned a)
{
    asm volatile("ldmatrix.sync.aligned.m8n8.x4.shared.b16 {%0,%1,%2,%3},[%4];"
        : "=r"(r[0]), "=r"(r[1]), "=r"(r[2]), "=r"(r[3]) : "r"(a));
}
__device__ __forceinline__ void ldmB2T(unsigned* r, unsigned a)
{
    asm volatile("ldmatrix.sync.aligned.m8n8.x2.trans.shared.b16 {%0,%1},[%2];"
        : "=r"(r[0]), "=r"(r[1]) : "r"(a));
}
__device__ __forceinline__ void cpa16(unsigned dst, const void* src)
{ asm volatile("cp.async.cg.shared.global [%0], [%1], 16;" :: "r"(dst), "l"(src)); }

extern __shared__ __nv_bfloat16 s_dyn[];

__global__ void __launch_bounds__(256) k_logits_mma(const float* __restrict__ bias,
                                                    unsigned fk0, unsigned fk1)
{
    int t = threadIdx.x, w = t >> 5, lane = t & 31;
    int n0 = blockIdx.x * NT;
    unsigned sb = (unsigned)__cvta_generic_to_shared(s_dyn);
    const __nv_bfloat16* Wp[2] = {g_W1, g_W2};
    float acc[4][2][4];
#pragma unroll
    for (int i = 0; i < 4; i++)
#pragma unroll
        for (int j = 0; j < 2; j++)
#pragma unroll
            for (int q = 0; q < 4; q++) acc[i][j][q] = 0.f;

    {
        unsigned base = sb;
        for (int e = t; e < 512; e += 256) {
            int spl = e >> 8, m = (e >> 2) & 63, f = e & 3;
            cpa16(base + (spl * SA_SPL + m * SA_STR + f * 8) * 2,
                  &g_As[(size_t)(spl * B + m) * KV + f * 8]);
        }
        for (int e = t; e < 1024; e += 256) {
            int spl = e >> 9, k = (e >> 4) & 31, f = e & 15;
            cpa16(base + (2 * SA_SPL + spl * SW_SPL + k * SW_STR + f * 8) * 2,
                  &Wp[spl][(size_t)k * V + n0 + f * 8]);
        }
        asm volatile("cp.async.commit_group;");
    }

    for (int ch = 0; ch < NCHUNK; ch++) {
        if (ch + 1 < NCHUNK) {
            int kt = (ch + 1) * KCH;
            unsigned base = sb + ((ch + 1) & 1) * BUFE * 2;
            for (int e = t; e < 512; e += 256) {
                int spl = e >> 8, m = (e >> 2) & 63, f = e & 3;
                cpa16(base + (spl * SA_SPL + m * SA_STR + f * 8) * 2,
                      &g_As[(size_t)(spl * B + m) * KV + kt + f * 8]);
            }
            for (int e = t; e < 1024; e += 256) {
                int spl = e >> 9, k = (e >> 4) & 31, f = e & 15;
                cpa16(base + (2 * SA_SPL + spl * SW_SPL + k * SW_STR + f * 8) * 2,
                      &Wp[spl][(size_t)(kt + k) * V + n0 + f * 8]);
            }
            asm volatile("cp.async.commit_group;");
            asm volatile("cp.async.wait_group 1;");
        } else {
            asm volatile("cp.async.wait_group 0;");
        }
        __syncthreads();
        __nv_bfloat16* sA = s_dyn + (ch & 1) * BUFE;
        __nv_bfloat16* sW = sA + 2 * SA_SPL;
#pragma unroll
        for (int ks = 0; ks < 2; ks++) {
            unsigned bfr[2][2][2];
            int kr = ks * 16 + (lane & 15);
#pragma unroll
            for (int spl = 0; spl < 2; spl++)
#pragma unroll
                for (int nt = 0; nt < 2; nt++)
                    ldmB2T(bfr[spl][nt], (unsigned)__cvta_generic_to_shared(
                        &sW[spl * SW_SPL + kr * SW_STR + w * 16 + nt * 8]));
            int am = lane & 15, ac = ks * 16 + ((lane >> 4) << 3);
#pragma unroll
            for (int mt = 0; mt < 4; mt++) {
                unsigned afr[2][4];
#pragma unroll
                for (int spl = 0; spl < 2; spl++)
                    ldmA4(afr[spl], (unsigned)__cvta_generic_to_shared(
                        &sA[spl * SA_SPL + (mt * 16 + am) * SA_STR + ac]));
#pragma unroll
                for (int nt = 0; nt < 2; nt++) {
                    float* d = acc[mt][nt];
                    mma16816(d, afr[0], bfr[0][nt]);
                    mma16816(d, afr[0], bfr[1][nt]);
                    mma16816(d, afr[1], bfr[0][nt]);
                }
            }
        }
        __syncthreads();
    }
    int g = lane >> 2, c2 = (lane & 3) * 2;
#pragma unroll
    for (int mt = 0; mt < 4; mt++)
#pragma unroll
        for (int nt = 0; nt < 2; nt++) {
            int col = n0 + w * 16 + nt * 8 + c2;
            float b0 = bias[col], b1 = bias[col + 1];
            int r0 = mt * 16 + g, r1 = r0 + 8;
            unsigned o0, o1;
            unsigned j00 = (unsigned)(r0 * V + col);
            tf2x32(fk0, fk1, 0u, j00, &o0, &o1);
            float g00 = gumbel_from_bits(o0 ^ o1);
            tf2x32(fk0, fk1, 0u, j00 + 1u, &o0, &o1);
            float g01 = gumbel_from_bits(o0 ^ o1);
            unsigned j10 = (unsigned)(r1 * V + col);
            tf2x32(fk0, fk1, 0u, j10, &o0, &o1);
            float g10 = gumbel_from_bits(o0 ^ o1);
            tf2x32(fk0, fk1, 0u, j10 + 1u, &o0, &o1);
            float g11 = gumbel_from_bits(o0 ^ o1);
            g_t[(size_t)r0 * V + col]     = acc[mt][nt][0] + b0 + g00;
            g_t[(size_t)r0 * V + col + 1] = acc[mt][nt][1] + b1 + g01;
            g_t[(size_t)r1 * V + col]     = acc[mt][nt][2] + b0 + g10;
            g_t[(size_t)r1 * V + col + 1] = acc[mt][nt][3] + b1 + g11;
        }
}

__global__ void k_softmax(float* __restrict__ out, int step, int steps,
                          const int* __restrict__ tptr)
{
    int b = blockIdx.x, t = threadIdx.x;
    int tb = *tptr;
    float temp = (tb >= 1 && tb < 100000) ? (float)tb : __int_as_float(tb);
    float inv = 1.0f / temp;
    const float* lg = g_t + (size_t)b * V;
    __shared__ float smx[256]; __shared__ int sai[256]; __shared__ float ssum[256];
    float mx = -1e30f; int ai = 0;
    for (int v = t; v < V; v += 256) {
        float x = lg[v] * inv;
        if (x > mx) { mx = x; ai = v; }
    }
    smx[t] = mx; sai[t] = ai;
    __syncthreads();
    for (int o = 128; o > 0; o >>= 1) {
        if (t < o) {
            if (smx[t + o] > smx[t] ||
                (smx[t + o] == smx[t] && sai[t + o] < sai[t])) {
                smx[t] = smx[t + o]; sai[t] = sai[t + o];
            }
        }
        __syncthreads();
    }
    float rowmax = smx[0];
    if (t == 0) g_prev[b] = sai[0];
    float s = 0.f;
    for (int v = t; v < V; v += 256) s += expf(lg[v] * inv - rowmax);
    ssum[t] = s;
    __syncthreads();
    for (int o = 128; o > 0; o >>= 1) {
        if (t < o) ssum[t] += ssum[t + o];
        __syncthreads();
    }
    float rinv = 1.0f / ssum[0];
    float* op = out + ((size_t)b * steps + step) * V;
    for (int v = t; v < V; v += 256)
        op[v] = expf(lg[v] * inv - rowmax) * rinv;
}

extern "C" void kernel_launch(void* const* d_in, const int* in_sizes, int n_in,
                              void* d_out, int out_size)
{
    const float* z     = (const float*)d_in[0];
    const float* w_z2m = (const float*)d_in[1];
    const float* b_z2m = (const float*)d_in[2];
    const float* bn1_g = (const float*)d_in[3];
    const float* bn1_b = (const float*)d_in[4];
    const float* emb   = (const float*)d_in[5];
    const float* bn2_g = (const float*)d_in[6];
    const float* bn2_b = (const float*)d_in[7];
    const float* w_in  = (const float*)d_in[8];
    const float* b_in  = (const float*)d_in[9];
    const float* w_q   = (const float*)d_in[10];
    const float* w_k   = (const float*)d_in[11];
    const float* w_v   = (const float*)d_in[12];
    const float* w_m1  = (const float*)d_in[13];
    const float* b_m1  = (const float*)d_in[14];
    const float* w_m2  = (const float*)d_in[15];
    const float* b_m2  = (const float*)d_in[16];
    const float* w_gx  = (const float*)d_in[17];
    const float* b_gx  = (const float*)d_in[18];
    const float* w_gm  = (const float*)d_in[19];
    const float* w_m2o = (const float*)d_in[20];
    const float* b_m2o = (const float*)d_in[21];
    const int*   tptr  = (const int*)d_in[23];
    float* out = (float*)d_out;
    int steps = out_size / (B * V);

    cudaFuncSetAttribute(k_logits_mma,
                         cudaFuncAttributeMaxDynamicSharedMemorySize, SMEMB);

    k_init<<<512, 256>>>();
    k_wsplit<<<64000, 256>>>(w_m2o);
    k_zpre<<<B, 128>>>(z, w_z2m, b_z2m);
    k_bn1<<<H, 64>>>(bn1_g, bn1_b);

    for (int s = 0; s < steps; s++) {
        unsigned fk0, fk1;
        tf2x32(0u, 42u, 0u, (unsigned)s, &fk0, &fk1);
        int ping = s & 1;

        k_embed_bn<<<SI, 64>>>(emb, bn2_g, bn2_b);
        k_inp<<<B, 128>>>(w_in, b_in);
        k_qkv<<<dim3(B, 14), 128>>>(ping, w_q, w_k, w_v);
        k_attn<<<dim3(B, NH), 256>>>();
        k_mlp1<<<dim3(B, MM), 128>>>(ping, w_m1, b_m1);
        k_mlp2g<<<dim3(B, MM), 128>>>(ping, w_m2, b_m2, w_gx, b_gx, w_gm);
        k_logits_mma<<<V / NT, 256, SMEMB>>>(b_m2o, fk0, fk1);
        k_softmax<<<B, 256>>>(out, s, steps, tptr);
    }
}